// round 17
// baseline (speedup 1.0000x reference)
#include <cuda_runtime.h>
#include <cuda_fp16.h>

// Problem constants (fixed by reference setup_inputs)
#define NN 8192
#define DD 64
#define NITER 20
#define REG_E 0.05f
#define INVN (1.0f / 8192.0f)
#define ALPHA 32768.0f                 // fp16 scale for K; cancels exactly
#define LN_ALPHA 10.397207708399179f   // ln(2^15)

#define FB 128                // persistent CTAs (1 per SM, co-resident)
#define FROWS (NN / FB)       // 64 rows per CTA
#define GR 4                  // rows per group
#define NG (FROWS / GR)       // 16 groups
#define GBYTES (GR * NN * 2)  // 65536 B per group tile
#define NBUF 3
#define PASSES (NITER + 1)    // 20 sinkhorn iters + 1 final-contraction pass
#define TOTSTEPS (PASSES * NG)   // 336

// Dynamic SMEM: 3 tile buffers + small tail
#define OFF_TAIL (NBUF * GBYTES)      // 196608
#define FUSED_SMEM (OFF_TAIL + 4096)  // 200704 (< 227 KB limit)

// Scratch: __device__ globals (no allocation allowed)
__device__ __half g_K16[(size_t)NN * NN];   // 128 MB: C16 then K16 in-place
__device__ float g_x2[NN];
__device__ float g_y2[NN];
__device__ float g_u[NN];                   // u/ALPHA (scale cancels)
__device__ float g_v[NN];
__device__ unsigned g_cmax_bits;
__device__ float g_cpart[FB][NN];           // 4 MB column partial sums
__device__ float g_partial[FB];
__device__ unsigned g_bcount;
__device__ unsigned g_bgen;

// ---------------------------------------------------------------------------
__global__ void init_kernel() {
    int j = blockIdx.x * blockDim.x + threadIdx.x;
    if (j < NN) g_v[j] = 1.0f;
    if (j == 0) { g_cmax_bits = 0u; g_bcount = 0u; }
}

// ---------------------------------------------------------------------------
__global__ void norms_kernel(const float* __restrict__ XP,
                             const float* __restrict__ XQ) {
    int row = blockIdx.x * blockDim.x + threadIdx.x;
    if (row >= NN) return;
    const float* X = blockIdx.y ? XQ : XP;
    float* out = blockIdx.y ? g_y2 : g_x2;
    const float4* p = (const float4*)(X + (size_t)row * DD);
    float s = 0.0f;
#pragma unroll
    for (int i = 0; i < DD / 4; i++) {
        float4 a = p[i];
        s += a.x * a.x + a.y * a.y + a.z * a.z + a.w * a.w;
    }
    out[row] = s;
}

// ---------------------------------------------------------------------------
// Tensor-core GEMM: C = max(x2 + y2 - 2*XP@XQ^T, 0) stored as fp16.
// ---------------------------------------------------------------------------
#define SROW 72
__global__ void __launch_bounds__(256) gemm_kernel(const float* __restrict__ XP,
                                                   const float* __restrict__ XQ) {
    __shared__ __half As[128 * SROW];
    __shared__ __half Bs[128 * SROW];
    __shared__ float red[256];

    const int tid = threadIdx.x;
    const int warp = tid >> 5, lane = tid & 31;
    const int wm = warp >> 2, wn = warp & 3;
    const int g = lane >> 2, t = lane & 3;
    const int bm = blockIdx.y, bn = blockIdx.x;

#pragma unroll
    for (int i = 0; i < 8; i++) {
        int idx = i * 256 + tid;
        int r = idx >> 4;
        int c4 = idx & 15;
        float4 a = *(const float4*)(XP + (size_t)(bm * 128 + r) * DD + c4 * 4);
        __half2 a01 = __floats2half2_rn(a.x, a.y);
        __half2 a23 = __floats2half2_rn(a.z, a.w);
        uint2 pa; pa.x = *(unsigned*)&a01; pa.y = *(unsigned*)&a23;
        *(uint2*)(As + r * SROW + c4 * 4) = pa;
        float4 b = *(const float4*)(XQ + (size_t)(bn * 128 + r) * DD + c4 * 4);
        __half2 b01 = __floats2half2_rn(b.x, b.y);
        __half2 b23 = __floats2half2_rn(b.z, b.w);
        uint2 pb; pb.x = *(unsigned*)&b01; pb.y = *(unsigned*)&b23;
        *(uint2*)(Bs + r * SROW + c4 * 4) = pb;
    }
    __syncthreads();

    float acc[4][4][4];
#pragma unroll
    for (int mt = 0; mt < 4; mt++)
#pragma unroll
        for (int nt = 0; nt < 4; nt++)
#pragma unroll
            for (int r = 0; r < 4; r++) acc[mt][nt][r] = 0.0f;

#pragma unroll
    for (int ks = 0; ks < 4; ks++) {
        const int k0 = ks * 16;
        unsigned af[4][4], bf[4][2];
#pragma unroll
        for (int mt = 0; mt < 4; mt++) {
            int row = wm * 64 + mt * 16;
            af[mt][0] = *(unsigned*)(As + (row + g) * SROW + k0 + 2 * t);
            af[mt][1] = *(unsigned*)(As + (row + g + 8) * SROW + k0 + 2 * t);
            af[mt][2] = *(unsigned*)(As + (row + g) * SROW + k0 + 2 * t + 8);
            af[mt][3] = *(unsigned*)(As + (row + g + 8) * SROW + k0 + 2 * t + 8);
        }
#pragma unroll
        for (int nt = 0; nt < 4; nt++) {
            int col = wn * 32 + nt * 8 + g;
            bf[nt][0] = *(unsigned*)(Bs + col * SROW + k0 + 2 * t);
            bf[nt][1] = *(unsigned*)(Bs + col * SROW + k0 + 2 * t + 8);
        }
#pragma unroll
        for (int mt = 0; mt < 4; mt++)
#pragma unroll
            for (int nt = 0; nt < 4; nt++) {
                asm volatile(
                    "mma.sync.aligned.m16n8k16.row.col.f32.f16.f16.f32 "
                    "{%0,%1,%2,%3},{%4,%5,%6,%7},{%8,%9},{%0,%1,%2,%3};\n"
                    : "+f"(acc[mt][nt][0]), "+f"(acc[mt][nt][1]),
                      "+f"(acc[mt][nt][2]), "+f"(acc[mt][nt][3])
                    : "r"(af[mt][0]), "r"(af[mt][1]), "r"(af[mt][2]), "r"(af[mt][3]),
                      "r"(bf[nt][0]), "r"(bf[nt][1]));
            }
    }

    float lmax = 0.0f;
#pragma unroll
    for (int mt = 0; mt < 4; mt++) {
        int r0 = bm * 128 + wm * 64 + mt * 16 + g;
        float xA = g_x2[r0], xB = g_x2[r0 + 8];
#pragma unroll
        for (int nt = 0; nt < 4; nt++) {
            int c0 = bn * 128 + wn * 32 + nt * 8 + 2 * t;
            float y0 = g_y2[c0], y1 = g_y2[c0 + 1];
            float v00 = fmaxf(xA + y0 - 2.0f * acc[mt][nt][0], 0.0f);
            float v01 = fmaxf(xA + y1 - 2.0f * acc[mt][nt][1], 0.0f);
            float v10 = fmaxf(xB + y0 - 2.0f * acc[mt][nt][2], 0.0f);
            float v11 = fmaxf(xB + y1 - 2.0f * acc[mt][nt][3], 0.0f);
            lmax = fmaxf(lmax, fmaxf(fmaxf(v00, v01), fmaxf(v10, v11)));
            *(__half2*)(g_K16 + (size_t)r0 * NN + c0) = __floats2half2_rn(v00, v01);
            *(__half2*)(g_K16 + (size_t)(r0 + 8) * NN + c0) = __floats2half2_rn(v10, v11);
        }
    }

    red[tid] = lmax;
    __syncthreads();
    for (int s = 128; s > 0; s >>= 1) {
        if (tid < s) red[tid] = fmaxf(red[tid], red[tid + s]);
        __syncthreads();
    }
    if (tid == 0) atomicMax(&g_cmax_bits, __float_as_uint(red[0]));
}

// ---------------------------------------------------------------------------
// In-place: K16 = ALPHA * exp(-C16 / (reg * Cmax))
// ---------------------------------------------------------------------------
__global__ void exp_kernel() {
    float cmax = __uint_as_float(g_cmax_bits);
    float s = -1.0f / (REG_E * cmax);
    uint4* K8 = (uint4*)g_K16;
    int total8 = NN * (NN / 8);
    int stride = gridDim.x * blockDim.x;
    for (int i = blockIdx.x * blockDim.x + threadIdx.x; i < total8; i += stride) {
        uint4 c = K8[i];
        float2 c0 = __half22float2(*(__half2*)&c.x);
        float2 c1 = __half22float2(*(__half2*)&c.y);
        float2 c2 = __half22float2(*(__half2*)&c.z);
        float2 c3 = __half22float2(*(__half2*)&c.w);
        __half2 h0 = __floats2half2_rn(__expf(c0.x * s) * ALPHA, __expf(c0.y * s) * ALPHA);
        __half2 h1 = __floats2half2_rn(__expf(c1.x * s) * ALPHA, __expf(c1.y * s) * ALPHA);
        __half2 h2 = __floats2half2_rn(__expf(c2.x * s) * ALPHA, __expf(c2.y * s) * ALPHA);
        __half2 h3 = __floats2half2_rn(__expf(c3.x * s) * ALPHA, __expf(c3.y * s) * ALPHA);
        uint4 o;
        o.x = *(unsigned*)&h0; o.y = *(unsigned*)&h1;
        o.z = *(unsigned*)&h2; o.w = *(unsigned*)&h3;
        K8[i] = o;
    }
}

// ---------------------------------------------------------------------------
// Grid-wide sense-reversal barrier (128 CTAs, 1/SM, all co-resident).
// ---------------------------------------------------------------------------
__device__ __forceinline__ void grid_bar() {
    __syncthreads();
    if (threadIdx.x == 0) {
        __threadfence();
        unsigned gen = *((volatile unsigned*)&g_bgen);
        if (atomicAdd(&g_bcount, 1u) == FB - 1) {
            g_bcount = 0;
            __threadfence();
            atomicAdd(&g_bgen, 1u);
        } else {
            while (*((volatile unsigned*)&g_bgen) == gen) {}
        }
        __threadfence();
    }
    __syncthreads();
}

__device__ __forceinline__ void mwait(unsigned mb, int ph) {
    unsigned done = 0;
    while (!done) {
        asm volatile(
            "{\n\t.reg .pred p;\n\t"
            "mbarrier.try_wait.parity.acquire.cta.shared::cta.b64 p, [%1], %2, 0x989680;\n\t"
            "selp.b32 %0, 1, 0, p;\n\t}"
            : "=r"(done) : "r"(mb), "r"(ph) : "memory");
    }
}

__device__ __forceinline__ void issue_tile(int step, int row_base,
                                           const unsigned* buf_s,
                                           const unsigned* mbar_s) {
    if (threadIdx.x == 0 && step < TOTSTEPS) {
        int g = step & (NG - 1);              // rows depend only on g (K constant)
        int b = step % NBUF;
        unsigned long long gsrc;
        const __half* src = g_K16 + (size_t)(row_base + g * GR) * NN;
        asm volatile("cvta.to.global.u64 %0, %1;" : "=l"(gsrc) : "l"(src));
        asm volatile("mbarrier.arrive.expect_tx.shared.b64 _, [%0], %1;"
                     :: "r"(mbar_s[b]), "r"((unsigned)GBYTES) : "memory");
        asm volatile("cp.async.bulk.shared::cta.global.mbarrier::complete_tx::bytes "
                     "[%0], [%1], %2, [%3];"
                     :: "r"(buf_s[b]), "l"(gsrc), "r"((unsigned)GBYTES), "r"(mbar_s[b])
                     : "memory");
    }
}

// ---------------------------------------------------------------------------
// Persistent Sinkhorn, software-pipelined across groups:
// step g:  u(g-1) from swarp  |  phase B(g-1) re-read from buf(g-1) (smem,
// NBUF=3 ring keeps it alive)  |  phase A dots(g) from buf(g) -> swarp[g&1]
// |  ONE syncthreads  |  refill slot (g-1)%3 with tile g+2.
// Nothing in the step waits on u of the same group; consumption rate tracks
// the DRAM cadence instead of the serial A->u->B chain.
// ---------------------------------------------------------------------------
__global__ void __launch_bounds__(512, 1) sink_kernel(float* __restrict__ out) {
    extern __shared__ __align__(128) unsigned char s_raw[];
    const int tid = threadIdx.x;
    const int blk = blockIdx.x;
    const int row_base = blk * FROWS;

    const uint4* bufs4[NBUF];
    unsigned buf_s[NBUF], mbar_s[NBUF];
    float* tail = (float*)(s_raw + OFF_TAIL);
    float4* swarp4 = (float4*)tail;       // [2][16] float4 = 128 floats
    float* sred = tail + 128;             // [512]
    unsigned long long* mbar = (unsigned long long*)(tail + 128 + 512);

#pragma unroll
    for (int b = 0; b < NBUF; b++) {
        bufs4[b] = (const uint4*)(s_raw + b * GBYTES);
        buf_s[b] = (unsigned)__cvta_generic_to_shared(s_raw + b * GBYTES);
        mbar_s[b] = (unsigned)__cvta_generic_to_shared(&mbar[b]);
    }
    if (tid == 0) {
#pragma unroll
        for (int b = 0; b < NBUF; b++)
            asm volatile("mbarrier.init.shared.b64 [%0], 1;" :: "r"(mbar_s[b]) : "memory");
    }
    __syncthreads();

    // Pipeline prologue: tiles 0 and 1 (tile G+2 issued at each step's end)
    issue_tile(0, row_base, buf_s, mbar_s);
    issue_tile(1, row_base, buf_s, mbar_s);

    int ph[NBUF] = {0, 0, 0};
    const int warp = tid >> 5, lane = tid & 31;

    float acc[16];
#pragma unroll
    for (int k = 0; k < 16; k++) acc[k] = 0.0f;

    int G = 0;

    for (int p = 0; p < NITER; p++) {
        // register-cache fp32 v for this thread's 16 columns
        float vr[16];
        {
            const float4* vp = (const float4*)(g_v + tid * 16);
#pragma unroll
            for (int q = 0; q < 4; q++) {
                float4 vv = vp[q];
                vr[q * 4 + 0] = vv.x; vr[q * 4 + 1] = vv.y;
                vr[q * 4 + 2] = vv.z; vr[q * 4 + 3] = vv.w;
            }
        }

        // ---- prologue step (g = 0): dots only
        {
            const int b = G % NBUF;
            mwait(mbar_s[b], ph[b]); ph[b] ^= 1;
            const uint4* KU = bufs4[b];
            float d[GR];
#pragma unroll
            for (int r = 0; r < GR; r++) {
                uint4 k0 = KU[r * 1024 + tid * 2];
                uint4 k1 = KU[r * 1024 + tid * 2 + 1];
                float s = 0.0f;
                float2 f;
                f = __half22float2(*(__half2*)&k0.x); s += f.x * vr[0] + f.y * vr[1];
                f = __half22float2(*(__half2*)&k0.y); s += f.x * vr[2] + f.y * vr[3];
                f = __half22float2(*(__half2*)&k0.z); s += f.x * vr[4] + f.y * vr[5];
                f = __half22float2(*(__half2*)&k0.w); s += f.x * vr[6] + f.y * vr[7];
                f = __half22float2(*(__half2*)&k1.x); s += f.x * vr[8] + f.y * vr[9];
                f = __half22float2(*(__half2*)&k1.y); s += f.x * vr[10] + f.y * vr[11];
                f = __half22float2(*(__half2*)&k1.z); s += f.x * vr[12] + f.y * vr[13];
                f = __half22float2(*(__half2*)&k1.w); s += f.x * vr[14] + f.y * vr[15];
                d[r] = s;
            }
#pragma unroll
            for (int r = 0; r < GR; r++)
#pragma unroll
                for (int off = 16; off; off >>= 1)
                    d[r] += __shfl_xor_sync(0xffffffffu, d[r], off);
            if (lane == 0)
                swarp4[(G & 1) * 16 + warp] = make_float4(d[0], d[1], d[2], d[3]);
            __syncthreads();
            issue_tile(G + 2, row_base, buf_s, mbar_s);
            G++;
        }

        // ---- steady steps g = 1..15
        for (int g = 1; g < NG; g++) {
            // u(g-1): all threads, from per-warp float4 partials (broadcast LDS)
            float uv[GR];
            {
                const float4* sp = swarp4 + ((G - 1) & 1) * 16;
                float4 t = sp[0];
#pragma unroll
                for (int w = 1; w < 16; w++) {
                    float4 q = sp[w];
                    t.x += q.x; t.y += q.y; t.z += q.z; t.w += q.w;
                }
                uv[0] = INVN / t.x; uv[1] = INVN / t.y;
                uv[2] = INVN / t.z; uv[3] = INVN / t.w;
            }
            if (tid < GR) g_u[row_base + (g - 1) * GR + tid] = uv[tid];

            // phase B(g-1): re-read from the still-alive ring buffer
            {
                const uint4* KB = bufs4[(G - 1) % NBUF];
#pragma unroll
                for (int r = 0; r < GR; r++) {
                    float u = uv[r];
                    uint4 k0 = KB[r * 1024 + tid * 2];
                    uint4 k1 = KB[r * 1024 + tid * 2 + 1];
                    float2 f;
                    f = __half22float2(*(__half2*)&k0.x); acc[0] += f.x * u; acc[1] += f.y * u;
                    f = __half22float2(*(__half2*)&k0.y); acc[2] += f.x * u; acc[3] += f.y * u;
                    f = __half22float2(*(__half2*)&k0.z); acc[4] += f.x * u; acc[5] += f.y * u;
                    f = __half22float2(*(__half2*)&k0.w); acc[6] += f.x * u; acc[7] += f.y * u;
                    f = __half22float2(*(__half2*)&k1.x); acc[8] += f.x * u; acc[9] += f.y * u;
                    f = __half22float2(*(__half2*)&k1.y); acc[10] += f.x * u; acc[11] += f.y * u;
                    f = __half22float2(*(__half2*)&k1.z); acc[12] += f.x * u; acc[13] += f.y * u;
                    f = __half22float2(*(__half2*)&k1.w); acc[14] += f.x * u; acc[15] += f.y * u;
                }
            }

            // phase A dots(g)
            {
                const int b = G % NBUF;
                mwait(mbar_s[b], ph[b]); ph[b] ^= 1;
                const uint4* KU = bufs4[b];
                float d[GR];
#pragma unroll
                for (int r = 0; r < GR; r++) {
                    uint4 k0 = KU[r * 1024 + tid * 2];
                    uint4 k1 = KU[r * 1024 + tid * 2 + 1];
                    float s = 0.0f;
                    float2 f;
                    f = __half22float2(*(__half2*)&k0.x); s += f.x * vr[0] + f.y * vr[1];
                    f = __half22float2(*(__half2*)&k0.y); s += f.x * vr[2] + f.y * vr[3];
                    f = __half22float2(*(__half2*)&k0.z); s += f.x * vr[4] + f.y * vr[5];
                    f = __half22float2(*(__half2*)&k0.w); s += f.x * vr[6] + f.y * vr[7];
                    f = __half22float2(*(__half2*)&k1.x); s += f.x * vr[8] + f.y * vr[9];
                    f = __half22float2(*(__half2*)&k1.y); s += f.x * vr[10] + f.y * vr[11];
                    f = __half22float2(*(__half2*)&k1.z); s += f.x * vr[12] + f.y * vr[13];
                    f = __half22float2(*(__half2*)&k1.w); s += f.x * vr[14] + f.y * vr[15];
                    d[r] = s;
                }
#pragma unroll
                for (int r = 0; r < GR; r++)
#pragma unroll
                    for (int off = 16; off; off >>= 1)
                        d[r] += __shfl_xor_sync(0xffffffffu, d[r], off);
                if (lane == 0)
                    swarp4[(G & 1) * 16 + warp] = make_float4(d[0], d[1], d[2], d[3]);
            }
            __syncthreads();
            issue_tile(G + 2, row_base, buf_s, mbar_s);
            G++;
        }

        // ---- drain: u(15) + phase B(15)
        {
            float uv[GR];
            const float4* sp = swarp4 + ((G - 1) & 1) * 16;
            float4 t = sp[0];
#pragma unroll
            for (int w = 1; w < 16; w++) {
                float4 q = sp[w];
                t.x += q.x; t.y += q.y; t.z += q.z; t.w += q.w;
            }
            uv[0] = INVN / t.x; uv[1] = INVN / t.y;
            uv[2] = INVN / t.z; uv[3] = INVN / t.w;
            if (tid < GR) g_u[row_base + (NG - 1) * GR + tid] = uv[tid];

            const uint4* KB = bufs4[(G - 1) % NBUF];
#pragma unroll
            for (int r = 0; r < GR; r++) {
                float u = uv[r];
                uint4 k0 = KB[r * 1024 + tid * 2];
                uint4 k1 = KB[r * 1024 + tid * 2 + 1];
                float2 f;
                f = __half22float2(*(__half2*)&k0.x); acc[0] += f.x * u; acc[1] += f.y * u;
                f = __half22float2(*(__half2*)&k0.y); acc[2] += f.x * u; acc[3] += f.y * u;
                f = __half22float2(*(__half2*)&k0.z); acc[4] += f.x * u; acc[5] += f.y * u;
                f = __half22float2(*(__half2*)&k0.w); acc[6] += f.x * u; acc[7] += f.y * u;
                f = __half22float2(*(__half2*)&k1.x); acc[8] += f.x * u; acc[9] += f.y * u;
                f = __half22float2(*(__half2*)&k1.y); acc[10] += f.x * u; acc[11] += f.y * u;
                f = __half22float2(*(__half2*)&k1.z); acc[12] += f.x * u; acc[13] += f.y * u;
                f = __half22float2(*(__half2*)&k1.w); acc[14] += f.x * u; acc[15] += f.y * u;
            }
        }

        // write column partials, reset accumulators
        {
            float4* outp = (float4*)(g_cpart[blk] + tid * 16);
            outp[0] = make_float4(acc[0], acc[1], acc[2], acc[3]);
            outp[1] = make_float4(acc[4], acc[5], acc[6], acc[7]);
            outp[2] = make_float4(acc[8], acc[9], acc[10], acc[11]);
            outp[3] = make_float4(acc[12], acc[13], acc[14], acc[15]);
#pragma unroll
            for (int k = 0; k < 16; k++) acc[k] = 0.0f;
        }
        grid_bar();

        // cooperative v-reduce: CTA owns 64 columns
        {
            int c0 = blk * 64;
            int col = tid & 63;
            int part = tid >> 6;       // 0..7, 16 chunks each
            float s = 0.0f;
#pragma unroll
            for (int k = 0; k < 16; k++) s += g_cpart[part * 16 + k][c0 + col];
            sred[part * 64 + col] = s;
            __syncthreads();
            if (tid < 64) {
                float t = 0.0f;
#pragma unroll
                for (int q = 0; q < 8; q++) t += sred[q * 64 + tid];
                g_v[c0 + tid] = INVN / t;
            }
        }
        grid_bar();
    }

    // -------- final pass: sum C .* plan, C = (lnALPHA - lnK)*reg*cmax --------
    float sigma = REG_E * __uint_as_float(g_cmax_bits);
    float vr[16];
    {
        const float4* vp = (const float4*)(g_v + tid * 16);
#pragma unroll
        for (int q = 0; q < 4; q++) {
            float4 vv = vp[q];
            vr[q * 4 + 0] = vv.x; vr[q * 4 + 1] = vv.y;
            vr[q * 4 + 2] = vv.z; vr[q * 4 + 3] = vv.w;
        }
    }
    float facc = 0.0f;
    for (int g = 0; g < NG; g++, G++) {
        const int b = G % NBUF;
        mwait(mbar_s[b], ph[b]); ph[b] ^= 1;
        const uint4* KU = bufs4[b];
        uint4 kreg[GR][2];
#pragma unroll
        for (int r = 0; r < GR; r++) {
            kreg[r][0] = KU[r * 1024 + tid * 2];
            kreg[r][1] = KU[r * 1024 + tid * 2 + 1];
        }
        __syncthreads();             // loads done -> buffer free
        issue_tile(G + 2, row_base, buf_s, mbar_s);   // no-op past end
#pragma unroll
        for (int r = 0; r < GR; r++) {
            float u = __ldg(&g_u[row_base + g * GR + r]);
            float rs = 0.0f;
#pragma unroll
            for (int j = 0; j < 2; j++) {
                float2 f0 = __half22float2(*(__half2*)&kreg[r][j].x);
                float2 f1 = __half22float2(*(__half2*)&kreg[r][j].y);
                float2 f2 = __half22float2(*(__half2*)&kreg[r][j].z);
                float2 f3 = __half22float2(*(__half2*)&kreg[r][j].w);
                rs += f0.x * vr[j * 8 + 0] * (LN_ALPHA - __logf(f0.x));
                rs += f0.y * vr[j * 8 + 1] * (LN_ALPHA - __logf(f0.y));
                rs += f1.x * vr[j * 8 + 2] * (LN_ALPHA - __logf(f1.x));
                rs += f1.y * vr[j * 8 + 3] * (LN_ALPHA - __logf(f1.y));
                rs += f2.x * vr[j * 8 + 4] * (LN_ALPHA - __logf(f2.x));
                rs += f2.y * vr[j * 8 + 5] * (LN_ALPHA - __logf(f2.y));
                rs += f3.x * vr[j * 8 + 6] * (LN_ALPHA - __logf(f3.x));
                rs += f3.y * vr[j * 8 + 7] * (LN_ALPHA - __logf(f3.y));
            }
            facc += u * rs;
        }
    }
    facc *= sigma;

    // block reduce -> g_partial[blk]
    {
        __syncthreads();
        sred[tid] = facc;
        __syncthreads();
        for (int s = 256; s > 0; s >>= 1) {
            if (tid < s) sred[tid] += sred[tid + s];
            __syncthreads();
        }
        if (tid == 0) g_partial[blk] = sred[0];
    }
    grid_bar();

    if (blk == 0) {
        float s = (tid < FB) ? g_partial[tid] : 0.0f;
        sred[tid] = s;
        __syncthreads();
        for (int st = 256; st > 0; st >>= 1) {
            if (tid < st) sred[tid] += sred[tid + st];
            __syncthreads();
        }
        if (tid == 0) out[0] = sred[0];
    }
}

// ---------------------------------------------------------------------------
extern "C" void kernel_launch(void* const* d_in, const int* in_sizes, int n_in,
                              void* d_out, int out_size) {
    const float* XP = (const float*)d_in[0];
    const float* XQ = (const float*)d_in[1];
    float* out = (float*)d_out;

    cudaFuncSetAttribute(sink_kernel,
                         cudaFuncAttributeMaxDynamicSharedMemorySize, FUSED_SMEM);

    init_kernel<<<NN / 256, 256>>>();
    norms_kernel<<<dim3(NN / 256, 2), 256>>>(XP, XQ);
    gemm_kernel<<<dim3(NN / 128, NN / 128), 256>>>(XP, XQ);
    exp_kernel<<<8192, 256>>>();
    sink_kernel<<<FB, 512, FUSED_SMEM>>>(out);
}